// round 12
// baseline (speedup 1.0000x reference)
#include <cuda_runtime.h>
#include <math.h>

#define NS  1024
#define XD  128
#define HID 256
#define RPB 7          // i-rows per pair block
#define NBLK 147       // ceil(1024/7) -> one block per SM (147 <= 148)

typedef unsigned long long ull;

// scratch (allocation-free rule: __device__ globals)
__device__ float g_pxT[HID * NS];   // [k][j] : px transposed
__device__ float g_pybT[HID * NS];  // [k][i] : (y@W1y + b1) transposed
__device__ float g_diag[NS];        // T1[i,i]
__device__ float g_e[NS];           // exp(lse_i - ln N)
__device__ int   g_sync1;           // phase-1 barrier counter (self-resetting)
__device__ int   g_ctr;             // finish election counter (self-resetting)

// ---------------------------------------------------------------------------
// packed f32x2 helpers (sm_100+)
// ---------------------------------------------------------------------------
__device__ __forceinline__ ull dup2(float x) {
    ull r;
    asm("mov.b64 %0, {%1, %1};" : "=l"(r) : "f"(x));
    return r;
}

// acc2 += max(a2 + p2, 0) * w2   (ADD2 + 2x scalar MAX + FMA2)
__device__ __forceinline__ void relu_fma2(ull& acc, ull a2, ull p2, ull w2) {
    asm("{\n\t"
        ".reg .b64 v;\n\t"
        ".reg .f32 lo, hi;\n\t"
        "add.rn.f32x2 v, %1, %2;\n\t"
        "mov.b64 {lo, hi}, v;\n\t"
        "max.f32 lo, lo, 0f00000000;\n\t"
        "max.f32 hi, hi, 0f00000000;\n\t"
        "mov.b64 v, {lo, hi};\n\t"
        "fma.rn.f32x2 %0, v, %3, %0;\n\t"
        "}"
        : "+l"(acc) : "l"(a2), "l"(p2), "l"(w2));
}

// ---------------------------------------------------------------------------
// Fused persistent kernel: phase 1 = both GEMMs (128 tile-blocks), device
// barrier, phase 2 = pair loop (R11 config), fused finish.
// ---------------------------------------------------------------------------
struct SmemP1 {                      // 33792 B
    float xs[64][68];                // [d][n] transposed
    float ws[64][64];                // [d][h]
};
struct SmemP2 {                      // 18432 B
    ull py2[HID][8];                 // dup'd pyb_T[k][ii] (ii 7 = pad)
    ull w2[HID];                     // dup'd W2
};

__global__ __launch_bounds__(1024, 1) void fused_kernel(
    const float* __restrict__ X, const float* __restrict__ Y,
    const float* __restrict__ W1, const float* __restrict__ b1,
    const float* __restrict__ W2, const float* __restrict__ b2,
    float* __restrict__ out)
{
    __shared__ union { SmemP1 p1; SmemP2 p2; } sm;
    __shared__ float red_m[16][RPB];
    __shared__ float red_s[16][RPB];
    __shared__ int   s_last;
    __shared__ float sd[32], se[32];

    const int t   = threadIdx.x;
    const int bid = blockIdx.x;

    // ======================= PHASE 1: GEMMs =======================
    // 128 tiles: n-tile = bid&15, h-tile = (bid>>4)&3, z = bid>>6
    if (bid < 128) {
        const int z  = bid >> 6;
        const float* A = z ? Y : X;
        float* C = z ? g_pybT : g_pxT;
        const int n0 = (bid & 15) * 64;
        const int h0 = ((bid >> 4) & 3) * 64;
        const int tx = t & 31;        // n pair index
        const int ty = t >> 5;        // h pair index (warp-uniform)

        float acc[2][2] = {{0.f, 0.f}, {0.f, 0.f}};

        for (int k0 = 0; k0 < XD; k0 += 64) {
            __syncthreads();
            {   // xs: each thread one float4 along d, scatter transposed
                int n = t >> 4, d4 = (t & 15) * 4;
                float4 v = *(const float4*)&A[(n0 + n) * XD + k0 + d4];
                sm.p1.xs[d4 + 0][n] = v.x;
                sm.p1.xs[d4 + 1][n] = v.y;
                sm.p1.xs[d4 + 2][n] = v.z;
                sm.p1.xs[d4 + 3][n] = v.w;
            }
            {   // ws: each thread one float4
                int d = t >> 4, h4 = (t & 15) * 4;
                *(float4*)&sm.p1.ws[d][h4] =
                    *(const float4*)&W1[(z * XD + k0 + d) * HID + h0 + h4];
            }
            __syncthreads();
#pragma unroll 8
            for (int d = 0; d < 64; d++) {
                float2 a = *(const float2*)&sm.p1.ws[d][ty * 2];
                float2 b = *(const float2*)&sm.p1.xs[d][tx * 2];
                acc[0][0] = fmaf(a.x, b.x, acc[0][0]);
                acc[0][1] = fmaf(a.x, b.y, acc[0][1]);
                acc[1][0] = fmaf(a.y, b.x, acc[1][0]);
                acc[1][1] = fmaf(a.y, b.y, acc[1][1]);
            }
        }
#pragma unroll
        for (int i = 0; i < 2; i++) {
            int h = h0 + ty * 2 + i;
            float bias = z ? b1[h] : 0.f;
            float2 o = make_float2(acc[i][0] + bias, acc[i][1] + bias);
            *(float2*)&C[h * NS + n0 + tx * 2] = o;
        }
    }

    // =================== DEVICE-WIDE BARRIER ===================
    // All 147 blocks are co-resident (one per SM) -> spin is deadlock-free.
    __threadfence();
    __syncthreads();
    if (t == 0) {
        atomicAdd(&g_sync1, 1);
        while (*(volatile int*)&g_sync1 < NBLK) { }
    }
    __syncthreads();
    __threadfence();                  // acquire phase-1 writes

    // ======================= PHASE 2: PAIR =======================
    const int jp  = t & 511;          // j-pair index: j = 2jp, 2jp+1
    const int grp = t >> 9;           // k half
    const int i0  = bid * RPB;

    // duplicate pyb columns + W2 into packed smem (guarded tail)
#pragma unroll
    for (int r = 0; r < 2; r++) {
        int f = t + 1024 * r;         // 2048 entries
        int k = f >> 3, ii = f & 7;
        int idx = i0 + ii;
        float v = (ii < RPB && idx < NS) ? g_pybT[k * NS + idx] : 0.f;
        sm.p2.py2[k][ii] = dup2(v);
    }
    if (t < HID) sm.p2.w2[t] = dup2(W2[t]);
    __syncthreads();

    ull acc2[RPB];
#pragma unroll
    for (int ii = 0; ii < RPB; ii++) acc2[ii] = 0ull;

    const int kb = grp * (HID / 2);       // this group's k base
    const ull* pxu = (const ull*)g_pxT;   // row k: NS/2 = 512 packed pairs

    ull buf[2][4];
#pragma unroll
    for (int kk = 0; kk < 4; kk++)
        buf[0][kk] = pxu[(kb + kk) * (NS / 2) + jp];

#pragma unroll 1
    for (int kl = 0; kl < HID / 2; kl += 4) {
        const int cur = (kl >> 2) & 1, nxt = cur ^ 1;
        const int knl = (kl + 4) & (HID / 2 - 1);   // wraps at end (harmless)
#pragma unroll
        for (int kk = 0; kk < 4; kk++)
            buf[nxt][kk] = pxu[(kb + knl + kk) * (NS / 2) + jp];

        // batched w2 for this k-quad: 2 x LDS.128
        ulonglong2 w01 = *(const ulonglong2*)&sm.p2.w2[kb + kl];
        ulonglong2 w23 = *(const ulonglong2*)&sm.p2.w2[kb + kl + 2];
        const ull wv[4] = {w01.x, w01.y, w23.x, w23.y};

#pragma unroll
        for (int kk = 0; kk < 4; kk++) {
            const int k = kb + kl + kk;
            const ull p = buf[cur][kk];
            ulonglong2 a01 = *(const ulonglong2*)&sm.p2.py2[k][0];
            ulonglong2 a23 = *(const ulonglong2*)&sm.p2.py2[k][2];
            ulonglong2 a45 = *(const ulonglong2*)&sm.p2.py2[k][4];
            ull        a6  = sm.p2.py2[k][6];
            relu_fma2(acc2[0], a01.x, p, wv[kk]);
            relu_fma2(acc2[1], a01.y, p, wv[kk]);
            relu_fma2(acc2[2], a23.x, p, wv[kk]);
            relu_fma2(acc2[3], a23.y, p, wv[kk]);
            relu_fma2(acc2[4], a45.x, p, wv[kk]);
            relu_fma2(acc2[5], a45.y, p, wv[kk]);
            relu_fma2(acc2[6], a6,    p, wv[kk]);
        }
    }

    // ---- merge k-halves: reuse py2 smem as exchange, rounds of 4+3 ----
    ull (*xch)[512] = (ull(*)[512])sm.p2.py2;   // [4][512]
    union cvt { ull u; float2 f; };
    __syncthreads();                  // main loop done; py2 reusable
    if (grp == 1) {
#pragma unroll
        for (int ii = 0; ii < 4; ii++) xch[ii][jp] = acc2[ii];
    }
    __syncthreads();
    if (grp == 0) {
#pragma unroll
        for (int ii = 0; ii < 4; ii++) {
            cvt a, b; a.u = acc2[ii]; b.u = xch[ii][jp];
            a.f.x += b.f.x; a.f.y += b.f.y; acc2[ii] = a.u;
        }
    }
    __syncthreads();
    if (grp == 1) {
#pragma unroll
        for (int ii = 0; ii < 3; ii++) xch[ii][jp] = acc2[ii + 4];
    }
    __syncthreads();
    if (grp == 0) {
#pragma unroll
        for (int ii = 0; ii < 3; ii++) {
            cvt a, b; a.u = acc2[ii + 4]; b.u = xch[ii][jp];
            a.f.x += b.f.x; a.f.y += b.f.y; acc2[ii + 4] = a.u;
        }
    }

    const int warp = t >> 5, lane = t & 31;

    // ---- epilogue (group 0 only; warp-uniform branch) ----
    if (grp == 0) {
        const float bm1 = b2[0] - 1.0f;
        float m[RPB], s[RPB];
#pragma unroll
        for (int ii = 0; ii < RPB; ii++) {
            cvt c; c.u = acc2[ii];
            float v0 = c.f.x + bm1;
            float v1 = c.f.y + bm1;
            const int ig = i0 + ii;   // ig >= NS never matches 2jp <= 1023
            if (2 * jp == ig)     g_diag[ig] = v0;
            if (2 * jp + 1 == ig) g_diag[ig] = v1;
            float mm = fmaxf(v0, v1);
            s[ii] = expf(v0 - mm) + expf(v1 - mm);
            m[ii] = mm;
        }
#pragma unroll
        for (int off = 16; off > 0; off >>= 1) {
#pragma unroll
            for (int ii = 0; ii < RPB; ii++) {
                float om = __shfl_xor_sync(0xffffffffu, m[ii], off);
                float os = __shfl_xor_sync(0xffffffffu, s[ii], off);
                float M  = fmaxf(m[ii], om);
                s[ii] = s[ii] * expf(m[ii] - M) + os * expf(om - M);
                m[ii] = M;
            }
        }
        if (lane == 0) {
#pragma unroll
            for (int ii = 0; ii < RPB; ii++) {
                red_m[warp][ii] = m[ii];
                red_s[warp][ii] = s[ii];
            }
        }
    }
    __syncthreads();
    if (t < RPB && i0 + t < NS) {
        float M = red_m[0][t], S = red_s[0][t];
#pragma unroll
        for (int w = 1; w < 16; w++) {
            float om = red_m[w][t], os = red_s[w][t];
            float M2 = fmaxf(M, om);
            S = S * expf(M - M2) + os * expf(om - M2);
            M = M2;
        }
        float lse = M + logf(S);
        g_e[i0 + t] = expf(lse - logf((float)NS));
    }

    // ---- fused finish: last block reduces diag + e, writes the scalar ----
    __threadfence();
    __syncthreads();
    if (t == 0)
        s_last = (atomicAdd(&g_ctr, 1) == (int)gridDim.x - 1);
    __syncthreads();
    if (!s_last) return;
    __threadfence();                  // acquire other blocks' writes

    float d = g_diag[t];
    float e = g_e[t];
#pragma unroll
    for (int off = 16; off > 0; off >>= 1) {
        d += __shfl_xor_sync(0xffffffffu, d, off);
        e += __shfl_xor_sync(0xffffffffu, e, off);
    }
    if (lane == 0) { sd[warp] = d; se[warp] = e; }
    __syncthreads();
    if (t < 32) {
        float dd = sd[t], ee = se[t];
#pragma unroll
        for (int off = 16; off > 0; off >>= 1) {
            dd += __shfl_xor_sync(0xffffffffu, dd, off);
            ee += __shfl_xor_sync(0xffffffffu, ee, off);
        }
        if (t == 0) {
            out[0] = dd * (1.0f / NS) + 1.0f - ee * (1.0f / NS);
            g_ctr = 0;                // self-reset for graph replay
            g_sync1 = 0;
        }
    }
}

// ---------------------------------------------------------------------------
extern "C" void kernel_launch(void* const* d_in, const int* in_sizes, int n_in,
                              void* d_out, int out_size)
{
    const float* x  = (const float*)d_in[0];
    const float* y  = (const float*)d_in[1];
    const float* W1 = (const float*)d_in[2];
    const float* b1 = (const float*)d_in[3];
    const float* W2 = (const float*)d_in[4];
    const float* b2 = (const float*)d_in[5];

    fused_kernel<<<NBLK, 1024>>>(x, y, W1, b1, W2, b2, (float*)d_out);
}

// round 13
// speedup vs baseline: 1.1318x; 1.1318x over previous
#include <cuda_runtime.h>
#include <math.h>

#define NS   1024
#define XD   128
#define HID  256
#define RPB  7          // i-rows per pair block
#define NBLK 147        // one block per SM

#define KROWS_STG 8     // k-rows per stage per k-half
#define NSTG      16    // 128 k / 8
// dynamic smem layout (bytes):
//   [0,16384)          ull py2[256][8]     dup'd pyb
//   [16384,18432)      ull w2[256]         dup'd W2
//   [18432,149504)     ull pxs[2][2][8][512]   px stages [buf][half][row][jp]
//   [149504,149520)    uint64 mbar[2]
#define OFF_PY2 0
#define OFF_W2  16384
#define OFF_PX  18432
#define OFF_MB  149504
#define DYN_BYTES 149520
#define STG_HALF_BYTES (KROWS_STG * (NS/2) * 8)   // 32768
#define STG_BYTES (2 * STG_HALF_BYTES)            // 65536 per stage (both halves)

typedef unsigned long long ull;

// scratch (allocation-free rule: __device__ globals)
__device__ float g_pxT[HID * NS];   // [k][j] : px transposed
__device__ float g_pybT[HID * NS];  // [k][i] : (y@W1y + b1) transposed
__device__ float g_diag[NS];        // T1[i,i]
__device__ float g_e[NS];           // exp(lse_i - ln N)
__device__ int   g_ctr;             // finish election (self-resetting)

// ---------------------------------------------------------------------------
__device__ __forceinline__ unsigned smem_u32(const void* p) {
    unsigned a;
    asm("{ .reg .u64 t; cvta.to.shared.u64 t, %1; cvt.u32.u64 %0, t; }"
        : "=r"(a) : "l"(p));
    return a;
}

__device__ __forceinline__ ull dup2(float x) {
    ull r;
    asm("mov.b64 %0, {%1, %1};" : "=l"(r) : "f"(x));
    return r;
}

// acc2 += max(a2 + p2, 0) * w2   (ADD2 + 2x scalar MAX + FMA2)
__device__ __forceinline__ void relu_fma2(ull& acc, ull a2, ull p2, ull w2) {
    asm("{\n\t"
        ".reg .b64 v;\n\t"
        ".reg .f32 lo, hi;\n\t"
        "add.rn.f32x2 v, %1, %2;\n\t"
        "mov.b64 {lo, hi}, v;\n\t"
        "max.f32 lo, lo, 0f00000000;\n\t"
        "max.f32 hi, hi, 0f00000000;\n\t"
        "mov.b64 v, {lo, hi};\n\t"
        "fma.rn.f32x2 %0, v, %3, %0;\n\t"
        "}"
        : "+l"(acc) : "l"(a2), "l"(p2), "l"(w2));
}

__device__ __forceinline__ void mbar_init(unsigned a, unsigned cnt) {
    asm volatile("mbarrier.init.shared.b64 [%0], %1;" :: "r"(a), "r"(cnt) : "memory");
}
__device__ __forceinline__ void mbar_expect_tx(unsigned a, unsigned bytes) {
    asm volatile("mbarrier.arrive.expect_tx.shared.b64 _, [%0], %1;"
                 :: "r"(a), "r"(bytes) : "memory");
}
__device__ __forceinline__ void mbar_wait(unsigned a, unsigned parity) {
    unsigned done;
    asm volatile(
        "{\n\t.reg .pred p;\n\t"
        "mbarrier.try_wait.parity.acquire.cta.shared::cta.b64 p, [%1], %2;\n\t"
        "selp.b32 %0, 1, 0, p;\n\t}"
        : "=r"(done) : "r"(a), "r"(parity) : "memory");
    if (!done) {
        asm volatile(
            "{\n\t.reg .pred P1;\n\t"
            "WL_%=:\n\t"
            "mbarrier.try_wait.parity.acquire.cta.shared::cta.b64 P1, [%0], %1, 0x989680;\n\t"
            "@P1 bra.uni WD_%=;\n\t"
            "bra.uni WL_%=;\n\t"
            "WD_%=:\n\t}"
            :: "r"(a), "r"(parity) : "memory");
    }
}
__device__ __forceinline__ void bulk_g2s(unsigned dst, const void* src,
                                         unsigned bytes, unsigned mbar) {
    asm volatile(
        "cp.async.bulk.shared::cta.global.mbarrier::complete_tx::bytes "
        "[%0], [%1], %2, [%3];"
        :: "r"(dst), "l"(src), "r"(bytes), "r"(mbar) : "memory");
}

// ---------------------------------------------------------------------------
// GEMM (R11 config, proven): block tile 64h x 64n, 512 threads, 2h x 4n.
// ---------------------------------------------------------------------------
__global__ __launch_bounds__(512) void gemm_kernel(
    const float* __restrict__ X, const float* __restrict__ Y,
    const float* __restrict__ W1, const float* __restrict__ b1)
{
    const int z  = blockIdx.z;
    const float* A = z ? Y : X;
    float* C = z ? g_pybT : g_pxT;
    const int h0 = blockIdx.y * 64;
    const int n0 = blockIdx.x * 64;
    const int t  = threadIdx.x;
    const int tx = t & 15;
    const int ty = t >> 4;

    __shared__ float xs[64][68];
    __shared__ float ws[64][64];

    float acc[2][4];
#pragma unroll
    for (int i = 0; i < 2; i++)
#pragma unroll
        for (int j = 0; j < 4; j++) acc[i][j] = 0.f;

    for (int k0 = 0; k0 < XD; k0 += 64) {
        __syncthreads();
#pragma unroll
        for (int r = 0; r < 2; r++) {
            int f = t + 512 * r;
            int n = f >> 4, d4 = (f & 15) * 4;
            float4 v = *(const float4*)&A[(n0 + n) * XD + k0 + d4];
            xs[d4 + 0][n] = v.x;
            xs[d4 + 1][n] = v.y;
            xs[d4 + 2][n] = v.z;
            xs[d4 + 3][n] = v.w;
        }
#pragma unroll
        for (int r = 0; r < 2; r++) {
            int f = t + 512 * r;
            int d = f >> 4, h4 = (f & 15) * 4;
            *(float4*)&ws[d][h4] =
                *(const float4*)&W1[(z * XD + k0 + d) * HID + h0 + h4];
        }
        __syncthreads();
#pragma unroll 8
        for (int d = 0; d < 64; d++) {
            float2 a = *(const float2*)&ws[d][ty * 2];
            float4 b = *(const float4*)&xs[d][tx * 4];
            const float av[2] = {a.x, a.y};
            const float bv[4] = {b.x, b.y, b.z, b.w};
#pragma unroll
            for (int i = 0; i < 2; i++)
#pragma unroll
                for (int j = 0; j < 4; j++)
                    acc[i][j] = fmaf(av[i], bv[j], acc[i][j]);
        }
    }

#pragma unroll
    for (int i = 0; i < 2; i++) {
        int h = h0 + ty * 2 + i;
        float bias = z ? b1[h] : 0.f;
        float4 o = make_float4(acc[i][0] + bias, acc[i][1] + bias,
                               acc[i][2] + bias, acc[i][3] + bias);
        *(float4*)&C[h * NS + n0 + tx * 4] = o;
    }
}

// ---------------------------------------------------------------------------
// Pair kernel (R11 + TMA px pipeline): 147 blocks x 1024 threads, RPB=7,
// k-split x2 (grp = t>>9, jp = t&511). px streamed by cp.async.bulk into
// 2 stage buffers (8 k-rows per half per stage), consumed via LDS.64.
// ---------------------------------------------------------------------------
__global__ __launch_bounds__(1024) void pair_kernel(
    const float* __restrict__ W2, const float* __restrict__ b2,
    float* __restrict__ out)
{
    extern __shared__ char dynsm[];
    ull (*py2)[8] = (ull(*)[8])(dynsm + OFF_PY2);
    ull* w2s      = (ull*)(dynsm + OFF_W2);
    ull* pxs      = (ull*)(dynsm + OFF_PX);
    const unsigned mb0 = smem_u32(dynsm + OFF_MB);
    const unsigned mb1 = mb0 + 8;
    const unsigned pxs_u32 = smem_u32(dynsm + OFF_PX);

    __shared__ float red_m[16][RPB];
    __shared__ float red_s[16][RPB];
    __shared__ int   s_last;
    __shared__ float sd[32], se[32];

    const int t   = threadIdx.x;
    const int jp  = t & 511;
    const int grp = t >> 9;           // k half
    const int i0  = blockIdx.x * RPB;
    const int kb  = grp * (HID / 2);

    // mbarrier init + proxy fence
    if (t == 0) {
        mbar_init(mb0, 1);
        mbar_init(mb1, 1);
        asm volatile("fence.proxy.async.shared::cta;" ::: "memory");
    }

    // one-time: dup'd pyb columns + W2 into smem (guarded tail)
#pragma unroll
    for (int r = 0; r < 2; r++) {
        int f = t + 1024 * r;
        int k = f >> 3, ii = f & 7;
        int idx = i0 + ii;
        float v = (ii < RPB && idx < NS) ? g_pybT[k * NS + idx] : 0.f;
        py2[k][ii] = dup2(v);
    }
    if (t < HID) w2s[t] = dup2(W2[t]);
    __syncthreads();

    // prologue: issue stages 0 and 1
    if (t == 0) {
#pragma unroll
        for (int s = 0; s < 2; s++) {
            unsigned mb = s ? mb1 : mb0;
            mbar_expect_tx(mb, STG_BYTES);
#pragma unroll
            for (int h = 0; h < 2; h++) {
                unsigned dst = pxs_u32 + (s * 2 + h) * STG_HALF_BYTES;
                const float* src = g_pxT + (h * (HID / 2) + s * KROWS_STG) * NS;
                bulk_g2s(dst, src, STG_HALF_BYTES, s ? mb1 : mb0);
                (void)dst;
            }
        }
    }

    ull acc2[RPB];
#pragma unroll
    for (int ii = 0; ii < RPB; ii++) acc2[ii] = 0ull;

    // main loop over 16 stages of 8 k's
#pragma unroll 1
    for (int s = 0; s < NSTG; s++) {
        const int b = s & 1;
        mbar_wait(b ? mb1 : mb0, (s >> 1) & 1);

        const ull* pxstg = pxs + (size_t)(b * 2 + grp) * KROWS_STG * (NS / 2);

#pragma unroll
        for (int q = 0; q < 2; q++) {         // 2 k-quads per stage
            const int klq = s * KROWS_STG + q * 4;
            ulonglong2 w01 = *(const ulonglong2*)&w2s[kb + klq];
            ulonglong2 w23 = *(const ulonglong2*)&w2s[kb + klq + 2];
            const ull wv[4] = {w01.x, w01.y, w23.x, w23.y};
#pragma unroll
            for (int kk = 0; kk < 4; kk++) {
                const int k = kb + klq + kk;
                const ull p = pxstg[(q * 4 + kk) * (NS / 2) + jp];
                ulonglong2 a01 = *(const ulonglong2*)&py2[k][0];
                ulonglong2 a23 = *(const ulonglong2*)&py2[k][2];
                ulonglong2 a45 = *(const ulonglong2*)&py2[k][4];
                ull        a6  = py2[k][6];
                relu_fma2(acc2[0], a01.x, p, wv[kk]);
                relu_fma2(acc2[1], a01.y, p, wv[kk]);
                relu_fma2(acc2[2], a23.x, p, wv[kk]);
                relu_fma2(acc2[3], a23.y, p, wv[kk]);
                relu_fma2(acc2[4], a45.x, p, wv[kk]);
                relu_fma2(acc2[5], a45.y, p, wv[kk]);
                relu_fma2(acc2[6], a6,    p, wv[kk]);
            }
        }

        __syncthreads();                      // stage s fully consumed
        if (t == 0 && s + 2 < NSTG) {
            const int sn = s + 2;
            unsigned mb = b ? mb1 : mb0;      // reuse this stage's buffer
            mbar_expect_tx(mb, STG_BYTES);
#pragma unroll
            for (int h = 0; h < 2; h++) {
                unsigned dst = pxs_u32 + (b * 2 + h) * STG_HALF_BYTES;
                const float* src = g_pxT + (h * (HID / 2) + sn * KROWS_STG) * NS;
                bulk_g2s(dst, src, STG_HALF_BYTES, mb);
            }
        }
    }

    // ---- merge k-halves: reuse py2 (16KB) as exchange, rounds of 4+3 ----
    ull (*xch)[512] = (ull(*)[512])py2;
    union cvt { ull u; float2 f; };
    __syncthreads();
    if (grp == 1) {
#pragma unroll
        for (int ii = 0; ii < 4; ii++) xch[ii][jp] = acc2[ii];
    }
    __syncthreads();
    if (grp == 0) {
#pragma unroll
        for (int ii = 0; ii < 4; ii++) {
            cvt a, b; a.u = acc2[ii]; b.u = xch[ii][jp];
            a.f.x += b.f.x; a.f.y += b.f.y; acc2[ii] = a.u;
        }
    }
    __syncthreads();
    if (grp == 1) {
#pragma unroll
        for (int ii = 0; ii < 3; ii++) xch[ii][jp] = acc2[ii + 4];
    }
    __syncthreads();
    if (grp == 0) {
#pragma unroll
        for (int ii = 0; ii < 3; ii++) {
            cvt a, b; a.u = acc2[ii + 4]; b.u = xch[ii][jp];
            a.f.x += b.f.x; a.f.y += b.f.y; acc2[ii + 4] = a.u;
        }
    }

    const int warp = t >> 5, lane = t & 31;

    // ---- epilogue (group 0 only) ----
    if (grp == 0) {
        const float bm1 = b2[0] - 1.0f;
        float m[RPB], s[RPB];
#pragma unroll
        for (int ii = 0; ii < RPB; ii++) {
            cvt c; c.u = acc2[ii];
            float v0 = c.f.x + bm1;
            float v1 = c.f.y + bm1;
            const int ig = i0 + ii;
            if (2 * jp == ig)     g_diag[ig] = v0;
            if (2 * jp + 1 == ig) g_diag[ig] = v1;
            float mm = fmaxf(v0, v1);
            s[ii] = expf(v0 - mm) + expf(v1 - mm);
            m[ii] = mm;
        }
#pragma unroll
        for (int off = 16; off > 0; off >>= 1) {
#pragma unroll
            for (int ii = 0; ii < RPB; ii++) {
                float om = __shfl_xor_sync(0xffffffffu, m[ii], off);
                float os = __shfl_xor_sync(0xffffffffu, s[ii], off);
                float M  = fmaxf(m[ii], om);
                s[ii] = s[ii] * expf(m[ii] - M) + os * expf(om - M);
                m[ii] = M;
            }
        }
        if (lane == 0) {
#pragma unroll
            for (int ii = 0; ii < RPB; ii++) {
                red_m[warp][ii] = m[ii];
                red_s[warp][ii] = s[ii];
            }
        }
    }
    __syncthreads();
    if (t < RPB && i0 + t < NS) {
        float M = red_m[0][t], S = red_s[0][t];
#pragma unroll
        for (int w = 1; w < 16; w++) {
            float om = red_m[w][t], os = red_s[w][t];
            float M2 = fmaxf(M, om);
            S = S * expf(M - M2) + os * expf(om - M2);
            M = M2;
        }
        float lse = M + logf(S);
        g_e[i0 + t] = expf(lse - logf((float)NS));
    }

    // ---- fused finish ----
    __threadfence();
    __syncthreads();
    if (t == 0)
        s_last = (atomicAdd(&g_ctr, 1) == (int)gridDim.x - 1);
    __syncthreads();
    if (!s_last) return;
    __threadfence();

    float d = g_diag[t];
    float e = g_e[t];
#pragma unroll
    for (int off = 16; off > 0; off >>= 1) {
        d += __shfl_xor_sync(0xffffffffu, d, off);
        e += __shfl_xor_sync(0xffffffffu, e, off);
    }
    if (lane == 0) { sd[warp] = d; se[warp] = e; }
    __syncthreads();
    if (t < 32) {
        float dd = sd[t], ee = se[t];
#pragma unroll
        for (int off = 16; off > 0; off >>= 1) {
            dd += __shfl_xor_sync(0xffffffffu, dd, off);
            ee += __shfl_xor_sync(0xffffffffu, ee, off);
        }
        if (t == 0) {
            out[0] = dd * (1.0f / NS) + 1.0f - ee * (1.0f / NS);
            g_ctr = 0;
        }
    }
}

// ---------------------------------------------------------------------------
extern "C" void kernel_launch(void* const* d_in, const int* in_sizes, int n_in,
                              void* d_out, int out_size)
{
    const float* x  = (const float*)d_in[0];
    const float* y  = (const float*)d_in[1];
    const float* W1 = (const float*)d_in[2];
    const float* b1 = (const float*)d_in[3];
    const float* W2 = (const float*)d_in[4];
    const float* b2 = (const float*)d_in[5];

    cudaFuncSetAttribute(pair_kernel,
                         cudaFuncAttributeMaxDynamicSharedMemorySize, DYN_BYTES);

    dim3 gg(NS / 64, HID / 64, 2);
    gemm_kernel<<<gg, 512>>>(x, y, W1, b1);
    pair_kernel<<<NBLK, 1024, DYN_BYTES>>>(W2, b2, (float*)d_out);
}